// round 3
// baseline (speedup 1.0000x reference)
#include <cuda_runtime.h>
#include <math.h>

#define BN_NODES 81920
#define T_STEPS 16
#define FDIM 64
#define NE 327680
#define BATCH 4096
#define D1 1280
#define D2 640
#define D3 320

// ---------------- scratch (static device globals; no allocation) ----------------
__device__ float g_H[(size_t)BN_NODES * FDIM];          // hidden state
__device__ float g_Tx[(size_t)BN_NODES * 128];          // [Tx1 | Tx2]
__device__ float g_gx[(size_t)BN_NODES * 192];          // X-cheb outputs [xz|xr|xh]
__device__ float g_Z[(size_t)BN_NODES * FDIM];          // update gate
__device__ float g_HR[(size_t)BN_NODES * FDIM];         // H * R
__device__ float g_deg[BN_NODES];
__device__ int   g_cnt[BN_NODES];
__device__ int   g_cur[BN_NODES];
__device__ int   g_rp[BN_NODES + 1];
__device__ int   g_csrc[NE];
__device__ float g_cw[NE];
__device__ float g_nw[NE];
__device__ float g_Wx[192 * 192];
__device__ float g_Wh[192 * 128];
__device__ float g_Whh[192 * 64];
__device__ float g_m1[(size_t)BATCH * D2];
__device__ float g_m2[(size_t)BATCH * D3];

// packed f32x2 fma: d = a*b + d (elementwise on the two packed floats)
__device__ __forceinline__ void ffma2(unsigned long long& d, unsigned long long a,
                                      unsigned long long b) {
    asm volatile("fma.rn.f32x2 %0, %1, %2, %0;" : "+l"(d) : "l"(a), "l"(b));
}

union F2U { unsigned long long u; float2 f; };

__device__ __forceinline__ float sigm(float v) { return 1.f / (1.f + expf(-v)); }

// ---------------- prep kernels ----------------
__global__ void k_zero() {
    int i = blockIdx.x * blockDim.x + threadIdx.x;
    if (i < BN_NODES * FDIM) g_H[i] = 0.f;
    if (i < BN_NODES) { g_deg[i] = 0.f; g_cnt[i] = 0; g_cur[i] = 0; }
}

__global__ void k_deg(const int* __restrict__ ei, const float* __restrict__ ew) {
    int e = blockIdx.x * blockDim.x + threadIdx.x;
    if (e < NE) {
        atomicAdd(&g_deg[ei[e]], ew[e]);
        atomicAdd(&g_cnt[ei[NE + e]], 1);
    }
}

__global__ void k_nw(const int* __restrict__ ei, const float* __restrict__ ew) {
    int e = blockIdx.x * blockDim.x + threadIdx.x;
    if (e < NE) {
        int s = ei[e], d = ei[NE + e];
        float ds = g_deg[s], dd = g_deg[d];
        float is = ds > 0.f ? rsqrtf(ds) : 0.f;
        float id = dd > 0.f ? rsqrtf(dd) : 0.f;
        g_nw[e] = -is * ew[e] * id;
    }
}

// two-pass scan: per-thread sums, one 1024-wide Hillis-Steele, then prefix write
__global__ void k_scan() {
    __shared__ int sh[1024];
    const int PER = BN_NODES / 1024;  // 80
    int tid = threadIdx.x;
    int base = tid * PER;
    int sum = 0;
    for (int i = 0; i < PER; i++) sum += g_cnt[base + i];
    sh[tid] = sum;
    __syncthreads();
    for (int d = 1; d < 1024; d <<= 1) {
        int t = (tid >= d) ? sh[tid - d] : 0;
        __syncthreads();
        sh[tid] += t;
        __syncthreads();
    }
    int run = sh[tid] - sum;  // exclusive offset
    for (int i = 0; i < PER; i++) {
        g_rp[base + i] = run;
        run += g_cnt[base + i];
    }
    if (tid == 1023) g_rp[BN_NODES] = run;
}

__global__ void k_scatter(const int* __restrict__ ei) {
    int e = blockIdx.x * blockDim.x + threadIdx.x;
    if (e < NE) {
        int d = ei[NE + e];
        int pos = g_rp[d] + atomicAdd(&g_cur[d], 1);
        g_csrc[pos] = ei[e];
        g_cw[pos] = g_nw[e];
    }
}

// pack Chebyshev weights into concatenated [192 x Cout] matrices
__global__ void k_packW(const float* __restrict__ Wxz, const float* __restrict__ Wxr,
                        const float* __restrict__ Wxh, const float* __restrict__ Whz,
                        const float* __restrict__ Whr, const float* __restrict__ Whh) {
    int i = blockIdx.x * blockDim.x + threadIdx.x;
    const int NX = 192 * 192, NH = 192 * 128, NHH = 192 * 64;
    if (i < NX) {
        int r = i / 192, c = i % 192;
        int kk = r >> 6, ii = r & 63, g = c >> 6, j = c & 63;
        const float* W = (g == 0) ? Wxz : ((g == 1) ? Wxr : Wxh);
        g_Wx[i] = W[kk * 4096 + ii * 64 + j];
    } else if (i < NX + NH) {
        int q = i - NX;
        int r = q / 128, c = q % 128;
        int kk = r >> 6, ii = r & 63, g = c >> 6, j = c & 63;
        const float* W = (g == 0) ? Whz : Whr;
        g_Wh[q] = W[kk * 4096 + ii * 64 + j];
    } else if (i < NX + NH + NHH) {
        int q = i - NX - NH;
        int r = q >> 6, c = q & 63;
        int kk = r >> 6, ii = r & 63;
        g_Whh[q] = Whh[kk * 4096 + ii * 64 + c];
    }
}

// ---------------- SpMM: out[n,:] = scale * sum_e w_e * in[src_e,:]  (- sub[n,:]) ----------------
// warp per node; two half-warps process alternating edges with float4 lanes
__global__ void k_spmm(const float* __restrict__ in, int ldi,
                       float* __restrict__ out, int ldo,
                       const float* __restrict__ sub, int lds, float scale) {
    int node = blockIdx.x * 8 + (threadIdx.x >> 5);
    int lane = threadIdx.x & 31;
    int half = lane >> 4, hl = lane & 15;
    int s = g_rp[node], e = g_rp[node + 1];
    float ax = 0.f, ay = 0.f, az = 0.f, aw = 0.f;
    for (int i = s + half; i < e; i += 2) {
        int sr = g_csrc[i];
        float w = g_cw[i];
        float4 v = *(const float4*)(in + (size_t)sr * ldi + hl * 4);
        ax = fmaf(w, v.x, ax);
        ay = fmaf(w, v.y, ay);
        az = fmaf(w, v.z, az);
        aw = fmaf(w, v.w, aw);
    }
    ax += __shfl_down_sync(0xffffffffu, ax, 16);
    ay += __shfl_down_sync(0xffffffffu, ay, 16);
    az += __shfl_down_sync(0xffffffffu, az, 16);
    aw += __shfl_down_sync(0xffffffffu, aw, 16);
    if (half == 0) {
        ax *= scale; ay *= scale; az *= scale; aw *= scale;
        if (sub) {
            float4 sv = *(const float4*)(sub + (size_t)node * lds + hl * 4);
            ax -= sv.x; ay -= sv.y; az -= sv.z; aw -= sv.w;
        }
        *(float4*)(out + (size_t)node * ldo + hl * 4) = make_float4(ax, ay, az, aw);
    }
}

// ---------------- per-row epilogues ----------------
template <int EPI>
__device__ __forceinline__ void epi_row(int n, int j0, int c0, const float v[4],
                                        float* __restrict__ O, int ldo,
                                        const float* __restrict__ e0, const float* __restrict__ e1,
                                        const float* __restrict__ e2, const float* __restrict__ e3) {
    if (EPI == 0) {
        *(float4*)(O + (size_t)n * ldo + j0 + c0) = make_float4(v[0], v[1], v[2], v[3]);
    } else if (EPI == 1) {
        int c = j0 + c0;
        float4 o;
        o.x = fmaxf(v[0] + e0[c + 0], 0.f);
        o.y = fmaxf(v[1] + e0[c + 1], 0.f);
        o.z = fmaxf(v[2] + e0[c + 2], 0.f);
        o.w = fmaxf(v[3] + e0[c + 3], 0.f);
        *(float4*)(O + (size_t)n * ldo + c) = o;
    } else if (EPI == 2) {
        // gates: j0==0 -> Z = sigmoid(acc + gx_z + bxz + bhz)
        //        j0==64 -> HR = H * sigmoid(acc + gx_r + bxr + bhr)
        float4 gx4 = *(const float4*)(&g_gx[(size_t)n * 192 + j0 + c0]);
        if (j0 == 0) {
            float4 z;
            z.x = sigm(v[0] + gx4.x + e0[c0 + 0] + e1[c0 + 0]);
            z.y = sigm(v[1] + gx4.y + e0[c0 + 1] + e1[c0 + 1]);
            z.z = sigm(v[2] + gx4.z + e0[c0 + 2] + e1[c0 + 2]);
            z.w = sigm(v[3] + gx4.w + e0[c0 + 3] + e1[c0 + 3]);
            *(float4*)(&g_Z[(size_t)n * 64 + c0]) = z;
        } else {
            float4 h4 = *(const float4*)(&g_H[(size_t)n * 64 + c0]);
            float4 hr;
            hr.x = h4.x * sigm(v[0] + gx4.x + e2[c0 + 0] + e3[c0 + 0]);
            hr.y = h4.y * sigm(v[1] + gx4.y + e2[c0 + 1] + e3[c0 + 1]);
            hr.z = h4.z * sigm(v[2] + gx4.z + e2[c0 + 2] + e3[c0 + 2]);
            hr.w = h4.w * sigm(v[3] + gx4.w + e2[c0 + 3] + e3[c0 + 3]);
            *(float4*)(&g_HR[(size_t)n * 64 + c0]) = hr;
        }
    } else {
        // update: ht = tanh(acc + gx_h + bxh + bhh); H = relu(Z*H + (1-Z)*ht)
        float4 gx4 = *(const float4*)(&g_gx[(size_t)n * 192 + 128 + c0]);
        float4 h4 = *(const float4*)(&g_H[(size_t)n * 64 + c0]);
        float4 z4 = *(const float4*)(&g_Z[(size_t)n * 64 + c0]);
        float4 o;
        {
            float ht = tanhf(v[0] + gx4.x + e0[c0 + 0] + e1[c0 + 0]);
            o.x = fmaxf(z4.x * h4.x + (1.f - z4.x) * ht, 0.f);
        }
        {
            float ht = tanhf(v[1] + gx4.y + e0[c0 + 1] + e1[c0 + 1]);
            o.y = fmaxf(z4.y * h4.y + (1.f - z4.y) * ht, 0.f);
        }
        {
            float ht = tanhf(v[2] + gx4.z + e0[c0 + 2] + e1[c0 + 2]);
            o.z = fmaxf(z4.z * h4.z + (1.f - z4.z) * ht, 0.f);
        }
        {
            float ht = tanhf(v[3] + gx4.w + e0[c0 + 3] + e1[c0 + 3]);
            o.w = fmaxf(z4.w * h4.w + (1.f - z4.w) * ht, 0.f);
        }
        *(float4*)(&g_H[(size_t)n * 64 + c0]) = o;
    }
}

// ---------------- SGEMM with packed f32x2 FMA ----------------
// O[M,Cout] = [A0(:, 0:64) | A12(:, 0:128)] @ W, BM=128, BN=64, BK=16, 256 threads.
// Per-thread 8x4 via 4 row-pair packed accumulators x 4 cols.
template <int EPI>
__global__ void k_gemm(const float* __restrict__ A0, int lda0,
                       const float* __restrict__ A12,
                       const float* __restrict__ W, int ldw,
                       float* __restrict__ O, int ldo, int Kdim,
                       const float* __restrict__ e0, const float* __restrict__ e1,
                       const float* __restrict__ e2, const float* __restrict__ e3) {
    __shared__ float As[16][128];
    __shared__ float2 Bsd[16][64];   // duplicated B values {b,b}
    int tid = threadIdx.x;
    int tx = tid & 15, ty = tid >> 4;
    int m0 = blockIdx.x * 128;
    int j0 = blockIdx.y * 64;
    unsigned long long acc[4][4];
#pragma unroll
    for (int i = 0; i < 4; i++)
#pragma unroll
        for (int j = 0; j < 4; j++) acc[i][j] = 0ull;

    for (int kt = 0; kt < Kdim; kt += 16) {
        const float* Ap;
        int lda;
        if (A12 != nullptr && kt >= 64) { Ap = A12 + (kt - 64); lda = 128; }
        else { Ap = A0 + kt; lda = lda0; }
#pragma unroll
        for (int l = 0; l < 2; l++) {
            int idx = tid + l * 256;
            int m = idx >> 2;
            int kc = (idx & 3) * 4;
            float4 v = *(const float4*)(Ap + (size_t)(m0 + m) * lda + kc);
            As[kc + 0][m] = v.x; As[kc + 1][m] = v.y;
            As[kc + 2][m] = v.z; As[kc + 3][m] = v.w;
        }
        {
            int k = tid >> 4;
            int jc = (tid & 15) * 4;
            float4 w4 = *(const float4*)(W + (size_t)(kt + k) * ldw + j0 + jc);
            Bsd[k][jc + 0] = make_float2(w4.x, w4.x);
            Bsd[k][jc + 1] = make_float2(w4.y, w4.y);
            Bsd[k][jc + 2] = make_float2(w4.z, w4.z);
            Bsd[k][jc + 3] = make_float2(w4.w, w4.w);
        }
        __syncthreads();
#pragma unroll
        for (int kk = 0; kk < 16; kk++) {
            const unsigned long long* ap = (const unsigned long long*)(&As[kk][ty * 8]);
            const unsigned long long* bp = (const unsigned long long*)(&Bsd[kk][tx * 4]);
            unsigned long long a0 = ap[0], a1 = ap[1], a2 = ap[2], a3 = ap[3];
            unsigned long long b0 = bp[0], b1 = bp[1], b2 = bp[2], b3 = bp[3];
            ffma2(acc[0][0], a0, b0); ffma2(acc[0][1], a0, b1);
            ffma2(acc[0][2], a0, b2); ffma2(acc[0][3], a0, b3);
            ffma2(acc[1][0], a1, b0); ffma2(acc[1][1], a1, b1);
            ffma2(acc[1][2], a1, b2); ffma2(acc[1][3], a1, b3);
            ffma2(acc[2][0], a2, b0); ffma2(acc[2][1], a2, b1);
            ffma2(acc[2][2], a2, b2); ffma2(acc[2][3], a2, b3);
            ffma2(acc[3][0], a3, b0); ffma2(acc[3][1], a3, b1);
            ffma2(acc[3][2], a3, b2); ffma2(acc[3][3], a3, b3);
        }
        __syncthreads();
    }

    int c0 = tx * 4;
#pragma unroll
    for (int pi = 0; pi < 4; pi++) {
        float vlo[4], vhi[4];
#pragma unroll
        for (int j = 0; j < 4; j++) {
            F2U t; t.u = acc[pi][j];
            vlo[j] = t.f.x; vhi[j] = t.f.y;
        }
        int r0 = m0 + ty * 8 + 2 * pi;
        epi_row<EPI>(r0, j0, c0, vlo, O, ldo, e0, e1, e2, e3);
        epi_row<EPI>(r0 + 1, j0, c0, vhi, O, ldo, e0, e1, e2, e3);
    }
}

// ---------------- final tiny GEMM + softmax (warp per row) ----------------
__global__ void k_final(const float* __restrict__ W3, const float* __restrict__ b3,
                        float* __restrict__ out) {
    int row = blockIdx.x * 8 + (threadIdx.x >> 5);
    int lane = threadIdx.x & 31;
    if (row >= BATCH) return;
    float s0 = 0.f, s1 = 0.f;
    for (int k = lane; k < D3; k += 32) {
        float a = g_m2[(size_t)row * D3 + k];
        s0 = fmaf(a, W3[k * 2 + 0], s0);
        s1 = fmaf(a, W3[k * 2 + 1], s1);
    }
#pragma unroll
    for (int o = 16; o; o >>= 1) {
        s0 += __shfl_down_sync(0xffffffffu, s0, o);
        s1 += __shfl_down_sync(0xffffffffu, s1, o);
    }
    if (lane == 0) {
        float l0 = s0 + b3[0], l1 = s1 + b3[1];
        float m = fmaxf(l0, l1);
        float e0 = expf(l0 - m), e1 = expf(l1 - m);
        float inv = 1.f / (e0 + e1);
        out[row * 2 + 0] = e0 * inv;
        out[row * 2 + 1] = e1 * inv;
    }
}

// ---------------- host launcher ----------------
extern "C" void kernel_launch(void* const* d_in, const int* in_sizes, int n_in,
                              void* d_out, int out_size) {
    const float* x = (const float*)d_in[0];
    const int* ei = (const int*)d_in[1];
    const float* ew = (const float*)d_in[2];
    const float* Wxz = (const float*)d_in[3];  const float* bxz = (const float*)d_in[4];
    const float* Whz = (const float*)d_in[5];  const float* bhz = (const float*)d_in[6];
    const float* Wxr = (const float*)d_in[7];  const float* bxr = (const float*)d_in[8];
    const float* Whr = (const float*)d_in[9];  const float* bhr = (const float*)d_in[10];
    const float* Wxh = (const float*)d_in[11]; const float* bxh = (const float*)d_in[12];
    const float* Whh = (const float*)d_in[13]; const float* bhh = (const float*)d_in[14];
    const float* W1 = (const float*)d_in[15];  const float* b1 = (const float*)d_in[16];
    const float* W2 = (const float*)d_in[17];  const float* b2 = (const float*)d_in[18];
    const float* W3 = (const float*)d_in[19];  const float* b3 = (const float*)d_in[20];
    float* out = (float*)d_out;

    float *p_H, *p_Tx, *p_gx, *p_HR, *p_Wx, *p_Wh, *p_Whh, *p_m1, *p_m2;
    cudaGetSymbolAddress((void**)&p_H, g_H);
    cudaGetSymbolAddress((void**)&p_Tx, g_Tx);
    cudaGetSymbolAddress((void**)&p_gx, g_gx);
    cudaGetSymbolAddress((void**)&p_HR, g_HR);
    cudaGetSymbolAddress((void**)&p_Wx, g_Wx);
    cudaGetSymbolAddress((void**)&p_Wh, g_Wh);
    cudaGetSymbolAddress((void**)&p_Whh, g_Whh);
    cudaGetSymbolAddress((void**)&p_m1, g_m1);
    cudaGetSymbolAddress((void**)&p_m2, g_m2);

    const int EW_THREADS = 256;
    const int EW_GRID = (BN_NODES * FDIM + EW_THREADS - 1) / EW_THREADS;
    const int EDGE_GRID = (NE + 255) / 256;
    const int SPMM_GRID = BN_NODES / 8;

    // graph preprocessing
    k_zero<<<EW_GRID, EW_THREADS>>>();
    k_deg<<<EDGE_GRID, 256>>>(ei, ew);
    k_nw<<<EDGE_GRID, 256>>>(ei, ew);
    k_scan<<<1, 1024>>>();
    k_scatter<<<EDGE_GRID, 256>>>(ei);
    k_packW<<<(192 * (192 + 128 + 64) + 255) / 256, 256>>>(Wxz, Wxr, Wxh, Whz, Whr, Whh);

    for (int t = 0; t < T_STEPS; t++) {
        const float* xt = x + (size_t)t * BN_NODES * FDIM;

        // X basis: Tx1 = L X ; Tx2 = 2 L Tx1 - X ; gx = [X|Tx1|Tx2] @ Wx
        k_spmm<<<SPMM_GRID, 256>>>(xt, FDIM, p_Tx, 128, nullptr, 0, 1.f);
        k_spmm<<<SPMM_GRID, 256>>>(p_Tx, 128, p_Tx + 64, 128, xt, FDIM, 2.f);
        k_gemm<0><<<dim3(640, 3), 256>>>(xt, FDIM, p_Tx, p_Wx, 192, p_gx, 192, 192,
                                          nullptr, nullptr, nullptr, nullptr);

        // H basis + fused gates epilogue (writes g_Z, g_HR)
        k_spmm<<<SPMM_GRID, 256>>>(p_H, FDIM, p_Tx, 128, nullptr, 0, 1.f);
        k_spmm<<<SPMM_GRID, 256>>>(p_Tx, 128, p_Tx + 64, 128, p_H, FDIM, 2.f);
        k_gemm<2><<<dim3(640, 2), 256>>>(p_H, FDIM, p_Tx, p_Wh, 128, nullptr, 0, 192,
                                          bxz, bhz, bxr, bhr);

        // HR basis + fused update epilogue (writes g_H)
        k_spmm<<<SPMM_GRID, 256>>>(p_HR, FDIM, p_Tx, 128, nullptr, 0, 1.f);
        k_spmm<<<SPMM_GRID, 256>>>(p_Tx, 128, p_Tx + 64, 128, p_HR, FDIM, 2.f);
        k_gemm<3><<<dim3(640, 1), 256>>>(p_HR, FDIM, p_Tx, p_Whh, 64, nullptr, 0, 192,
                                          bxh, bhh, nullptr, nullptr);
    }

    // MLP head on H viewed as [4096, 1280]
    k_gemm<1><<<dim3(BATCH / 128, D2 / 64), 256>>>(p_H, D1, nullptr, W1, D2, p_m1, D2, D1,
                                                    b1, nullptr, nullptr, nullptr);
    k_gemm<1><<<dim3(BATCH / 128, D3 / 64), 256>>>(p_m1, D2, nullptr, W2, D3, p_m2, D3, D2,
                                                    b2, nullptr, nullptr, nullptr);
    k_final<<<BATCH / 8, 256>>>(W3, b3, out);
}

// round 5
// speedup vs baseline: 1.7598x; 1.7598x over previous
#include <cuda_runtime.h>
#include <math.h>
#include <cstdint>

#define BN_NODES 81920
#define T_STEPS 16
#define FDIM 64
#define NE 327680
#define BATCH 4096
#define D1 1280
#define D2 640
#define D3 320

// ---------------- scratch (static device globals; no allocation) ----------------
__device__ float g_H[(size_t)BN_NODES * FDIM];
__device__ float g_Tx[(size_t)BN_NODES * 128];          // [Tx1 | Tx2]
__device__ float g_gx[(size_t)BN_NODES * 192];          // X-cheb outputs [xz|xr|xh]
__device__ float g_Z[(size_t)BN_NODES * FDIM];
__device__ float g_HR[(size_t)BN_NODES * FDIM];
__device__ float g_deg[BN_NODES];
__device__ int   g_cnt[BN_NODES];
__device__ int   g_cur[BN_NODES];
__device__ int   g_rp[BN_NODES + 1];
__device__ int   g_bsum[80];
__device__ int   g_boff[80];
__device__ int   g_csrc[NE];
__device__ float g_cw[NE];
__device__ float g_nw[NE];
// fragment-packed tf32 weights: [kstep(24)][ntile][lane(32)][2]
__device__ float g_WxP[192 * 192];    // NT=24
__device__ float g_WhP[128 * 192];    // NT=16
__device__ float g_WhhP[64 * 192];    // NT=8
__device__ float g_m1[(size_t)BATCH * D2];
__device__ float g_m2[(size_t)BATCH * D3];

__device__ __forceinline__ float sigm(float v) { return 1.f / (1.f + expf(-v)); }

__device__ __forceinline__ uint32_t to_tf32(float f) {
    uint32_t r;
    asm("cvt.rna.tf32.f32 %0, %1;" : "=r"(r) : "f"(f));
    return r;
}

__device__ __forceinline__ void mma8(float* d, const uint32_t* a, uint32_t b0, uint32_t b1) {
    asm volatile(
        "mma.sync.aligned.m16n8k8.row.col.f32.tf32.tf32.f32 "
        "{%0,%1,%2,%3}, {%4,%5,%6,%7}, {%8,%9}, {%0,%1,%2,%3};"
        : "+f"(d[0]), "+f"(d[1]), "+f"(d[2]), "+f"(d[3])
        : "r"(a[0]), "r"(a[1]), "r"(a[2]), "r"(a[3]), "r"(b0), "r"(b1));
}

// ---------------- prep kernels ----------------
__global__ void k_zero() {
    int i = blockIdx.x * blockDim.x + threadIdx.x;
    if (i < BN_NODES * FDIM) g_H[i] = 0.f;
    if (i < BN_NODES) { g_deg[i] = 0.f; g_cnt[i] = 0; g_cur[i] = 0; }
}
__global__ void k_deg(const int* __restrict__ ei, const float* __restrict__ ew) {
    int e = blockIdx.x * blockDim.x + threadIdx.x;
    if (e < NE) {
        atomicAdd(&g_deg[ei[e]], ew[e]);
        atomicAdd(&g_cnt[ei[NE + e]], 1);
    }
}
__global__ void k_nw(const int* __restrict__ ei, const float* __restrict__ ew) {
    int e = blockIdx.x * blockDim.x + threadIdx.x;
    if (e < NE) {
        int s = ei[e], d = ei[NE + e];
        float ds = g_deg[s], dd = g_deg[d];
        float is = ds > 0.f ? rsqrtf(ds) : 0.f;
        float id = dd > 0.f ? rsqrtf(dd) : 0.f;
        g_nw[e] = -is * ew[e] * id;
    }
}
__global__ void k_scan1() {
    __shared__ int sh[1024];
    int b = blockIdx.x, tid = threadIdx.x;
    int i = b * 1024 + tid;
    int v = g_cnt[i];
    sh[tid] = v;
    __syncthreads();
    for (int d = 1; d < 1024; d <<= 1) {
        int t = (tid >= d) ? sh[tid - d] : 0;
        __syncthreads();
        sh[tid] += t;
        __syncthreads();
    }
    g_rp[i] = sh[tid] - v;
    if (tid == 1023) g_bsum[b] = sh[1023];
}
__global__ void k_scan2() {
    if (threadIdx.x == 0) {
        int run = 0;
        for (int b = 0; b < 80; b++) { g_boff[b] = run; run += g_bsum[b]; }
        g_rp[BN_NODES] = run;
    }
}
__global__ void k_scan3() {
    int b = blockIdx.x, tid = threadIdx.x;
    g_rp[b * 1024 + tid] += g_boff[b];
}
__global__ void k_scatter(const int* __restrict__ ei) {
    int e = blockIdx.x * blockDim.x + threadIdx.x;
    if (e < NE) {
        int d = ei[NE + e];
        int pos = g_rp[d] + atomicAdd(&g_cur[d], 1);
        g_csrc[pos] = ei[e];
        g_cw[pos] = g_nw[e];
    }
}

// pack weights into fragment order [ks][nt][lane][2], tf32-rounded.
// B[K][n] with K = kcheb*64 + i ; value = W[kcheb][i][n_group mapping]
__device__ __forceinline__ void pack_one(int o, int NT, float* dst,
                                         const float* W0, const float* W1, const float* W2) {
    int ks = o / (NT * 64);
    int r = o % (NT * 64);
    int nt = r / 64;
    int lr = r % 64;
    int lane = lr >> 1, reg = lr & 1;
    int tg = lane & 3, gq = lane >> 2;
    int k = ks * 8 + tg + reg * 4;
    int n = nt * 8 + gq;
    int kcheb = k >> 6, i = k & 63;
    int gsel = n >> 6, jj = n & 63;
    const float* W = (gsel == 0) ? W0 : ((gsel == 1) ? W1 : W2);
    float v = W[kcheb * 4096 + i * 64 + jj];
    dst[o] = __uint_as_float(to_tf32(v));
}
__global__ void k_packW(const float* __restrict__ Wxz, const float* __restrict__ Wxr,
                        const float* __restrict__ Wxh, const float* __restrict__ Whz,
                        const float* __restrict__ Whr, const float* __restrict__ Whh) {
    int i = blockIdx.x * blockDim.x + threadIdx.x;
    const int PX = 192 * 192, PH = 128 * 192, PHH = 64 * 192;
    if (i < PX) pack_one(i, 24, g_WxP, Wxz, Wxr, Wxh);
    else if (i < PX + PH) pack_one(i - PX, 16, g_WhP, Whz, Whr, Whr);
    else if (i < PX + PH + PHH) pack_one(i - PX - PH, 8, g_WhhP, Whh, Whh, Whh);
}

// ---------------- SpMM ----------------
__global__ void k_spmm(const float* __restrict__ in, int ldi,
                       float* __restrict__ out, int ldo,
                       const float* __restrict__ sub, int lds, float scale) {
    int node = blockIdx.x * 8 + (threadIdx.x >> 5);
    int lane = threadIdx.x & 31;
    int half = lane >> 4, hl = lane & 15;
    int s = g_rp[node], e = g_rp[node + 1];
    float ax = 0.f, ay = 0.f, az = 0.f, aw = 0.f;
    for (int i = s + half; i < e; i += 2) {
        int sr = g_csrc[i];
        float w = g_cw[i];
        float4 v = *(const float4*)(in + (size_t)sr * ldi + hl * 4);
        ax = fmaf(w, v.x, ax); ay = fmaf(w, v.y, ay);
        az = fmaf(w, v.z, az); aw = fmaf(w, v.w, aw);
    }
    ax += __shfl_down_sync(0xffffffffu, ax, 16);
    ay += __shfl_down_sync(0xffffffffu, ay, 16);
    az += __shfl_down_sync(0xffffffffu, az, 16);
    aw += __shfl_down_sync(0xffffffffu, aw, 16);
    if (half == 0) {
        ax *= scale; ay *= scale; az *= scale; aw *= scale;
        if (sub) {
            float4 sv = *(const float4*)(sub + (size_t)node * lds + hl * 4);
            ax -= sv.x; ay -= sv.y; az -= sv.z; aw -= sv.w;
        }
        *(float4*)(out + (size_t)node * ldo + hl * 4) = make_float4(ax, ay, az, aw);
    }
}

// ---------------- tf32 mma.sync GEMM, no-smem operand feed ----------------
// C[128 x NCOLS] per block = A[128 x 192] @ Bpacked
// 8 warps = 4 row-groups (32 rows = 2 m-tiles) x 2 col halves.
// EPI: 0 -> g_gx ; 2 -> GRU gates (Z, HR) ; 3 -> GRU update (H)
__device__ __forceinline__ void ldA_frag(const float* __restrict__ A0, int lda0,
                                         const float* __restrict__ A12,
                                         int row_base, int g, int tg, int ks,
                                         float aF[2][4]) {
    const float* Ap;
    int lda;
    if (A12 != nullptr && ks >= 8) { Ap = A12 + (ks * 8 - 64); lda = 128; }
    else { Ap = A0 + ks * 8; lda = lda0; }
#pragma unroll
    for (int mt = 0; mt < 2; mt++) {
        const float* ar = Ap + (size_t)(row_base + mt * 16 + g) * lda + tg;
        aF[mt][0] = ar[0];
        aF[mt][2] = ar[4];
        const float* ar8 = ar + (size_t)8 * lda;
        aF[mt][1] = ar8[0];
        aF[mt][3] = ar8[4];
    }
}

template <int NCOLS, int EPI>
__global__ void __launch_bounds__(256, 1) k_mma(
    const float* __restrict__ A0, int lda0, const float* __restrict__ A12,
    const float* __restrict__ Bp,
    const float* __restrict__ e0, const float* __restrict__ e1,
    const float* __restrict__ e2, const float* __restrict__ e3) {
    constexpr int NT = NCOLS / 8;
    constexpr int NT2 = NT / 2;
    __shared__ float s_bias[192];

    int tid = threadIdx.x;
    int lane = tid & 31, w = tid >> 5;
    int g = lane >> 2, tg = lane & 3;
    int m0 = blockIdx.x * 128;
    int row_base = m0 + (w >> 1) * 32;
    int ch = w & 1;
    int col_base = ch * (NCOLS / 2);
    int nt_base = ch * NT2;

    if (EPI == 2) {
        if (tid < 64) s_bias[tid] = e0[tid] + e1[tid];
        else if (tid < 128) s_bias[tid] = e2[tid - 64] + e3[tid - 64];
        __syncthreads();
    } else if (EPI == 3) {
        if (tid < 64) s_bias[tid] = e0[tid] + e1[tid];
        __syncthreads();
    }

    float acc[2][NT2][4];
#pragma unroll
    for (int mt = 0; mt < 2; mt++)
#pragma unroll
        for (int nt = 0; nt < NT2; nt++)
#pragma unroll
            for (int j = 0; j < 4; j++) acc[mt][nt][j] = 0.f;

    float aF[2][2][4];
    float2 bF[2][NT2];

    // prefetch ks=0
    ldA_frag(A0, lda0, A12, row_base, g, tg, 0, aF[0]);
#pragma unroll
    for (int nt = 0; nt < NT2; nt++)
        bF[0][nt] = *(const float2*)(Bp + (((size_t)0 * NT + nt_base + nt) * 32 + lane) * 2);

#pragma unroll 2
    for (int ks = 0; ks < 24; ks++) {
        int cur = ks & 1, nxt = cur ^ 1;
        if (ks < 23) {
            ldA_frag(A0, lda0, A12, row_base, g, tg, ks + 1, aF[nxt]);
#pragma unroll
            for (int nt = 0; nt < NT2; nt++)
                bF[nxt][nt] = *(const float2*)(Bp +
                    (((size_t)(ks + 1) * NT + nt_base + nt) * 32 + lane) * 2);
        }
        uint32_t a[2][4];
#pragma unroll
        for (int mt = 0; mt < 2; mt++)
#pragma unroll
            for (int j = 0; j < 4; j++) a[mt][j] = to_tf32(aF[cur][mt][j]);
#pragma unroll
        for (int nt = 0; nt < NT2; nt++) {
            uint32_t b0 = __float_as_uint(bF[cur][nt].x);
            uint32_t b1 = __float_as_uint(bF[cur][nt].y);
            mma8(acc[0][nt], a[0], b0, b1);
            mma8(acc[1][nt], a[1], b0, b1);
        }
    }

    // epilogue: per (mt, nt), rows (rg, rg+8), cols (col, col+1)
#pragma unroll
    for (int mt = 0; mt < 2; mt++) {
#pragma unroll
        for (int nt = 0; nt < NT2; nt++) {
#pragma unroll
            for (int half = 0; half < 2; half++) {
                int row = row_base + mt * 16 + g + half * 8;
                int col = col_base + nt * 8 + tg * 2;
                float v0 = acc[mt][nt][half * 2 + 0];
                float v1 = acc[mt][nt][half * 2 + 1];
                if (EPI == 0) {
                    *(float2*)(g_gx + (size_t)row * 192 + col) = make_float2(v0, v1);
                } else if (EPI == 2) {
                    float2 gx = *(const float2*)(g_gx + (size_t)row * 192 + col);
                    if (col < 64) {
                        float2 z;
                        z.x = sigm(v0 + gx.x + s_bias[col + 0]);
                        z.y = sigm(v1 + gx.y + s_bias[col + 1]);
                        *(float2*)(g_Z + (size_t)row * 64 + col) = z;
                    } else {
                        int c = col - 64;
                        float2 h = *(const float2*)(g_H + (size_t)row * 64 + c);
                        float2 hr;
                        hr.x = h.x * sigm(v0 + gx.x + s_bias[col + 0]);
                        hr.y = h.y * sigm(v1 + gx.y + s_bias[col + 1]);
                        *(float2*)(g_HR + (size_t)row * 64 + c) = hr;
                    }
                } else {  // EPI == 3
                    float2 gx = *(const float2*)(g_gx + (size_t)row * 192 + 128 + col);
                    float2 h = *(const float2*)(g_H + (size_t)row * 64 + col);
                    float2 z = *(const float2*)(g_Z + (size_t)row * 64 + col);
                    float ht0 = tanhf(v0 + gx.x + s_bias[col + 0]);
                    float ht1 = tanhf(v1 + gx.y + s_bias[col + 1]);
                    float2 o;
                    o.x = fmaxf(z.x * h.x + (1.f - z.x) * ht0, 0.f);
                    o.y = fmaxf(z.y * h.y + (1.f - z.y) * ht1, 0.f);
                    *(float2*)(g_H + (size_t)row * 64 + col) = o;
                }
            }
        }
    }
}

// ---------------- FFMA SGEMM for MLP head ----------------
__global__ void k_gemm_relu(const float* __restrict__ A0, int lda0,
                            const float* __restrict__ W, int ldw,
                            const float* __restrict__ bias,
                            float* __restrict__ O, int ldo, int Kdim) {
    __shared__ float As[16][128];
    __shared__ float Bs[16][64];
    int tid = threadIdx.x;
    int tx = tid & 15, ty = tid >> 4;
    int m0 = blockIdx.x * 128;
    int j0 = blockIdx.y * 64;
    float acc[8][4] = {};
    for (int kt = 0; kt < Kdim; kt += 16) {
        const float* Ap = A0 + kt;
#pragma unroll
        for (int l = 0; l < 2; l++) {
            int idx = tid + l * 256;
            int m = idx >> 2;
            int kc = (idx & 3) * 4;
            float4 v = *(const float4*)(Ap + (size_t)(m0 + m) * lda0 + kc);
            As[kc + 0][m] = v.x; As[kc + 1][m] = v.y;
            As[kc + 2][m] = v.z; As[kc + 3][m] = v.w;
        }
        {
            int k = tid >> 4;
            int jc = (tid & 15) * 4;
            *(float4*)&Bs[k][jc] = *(const float4*)(W + (size_t)(kt + k) * ldw + j0 + jc);
        }
        __syncthreads();
#pragma unroll
        for (int kk = 0; kk < 16; kk++) {
            float4 a0 = *(float4*)&As[kk][ty * 8];
            float4 a1 = *(float4*)&As[kk][ty * 8 + 4];
            float4 b = *(float4*)&Bs[kk][tx * 4];
            float av[8] = {a0.x, a0.y, a0.z, a0.w, a1.x, a1.y, a1.z, a1.w};
            float bv[4] = {b.x, b.y, b.z, b.w};
#pragma unroll
            for (int i = 0; i < 8; i++)
#pragma unroll
                for (int j = 0; j < 4; j++)
                    acc[i][j] = fmaf(av[i], bv[j], acc[i][j]);
        }
        __syncthreads();
    }
    float4 bb = *(const float4*)(bias + j0 + tx * 4);
#pragma unroll
    for (int i = 0; i < 8; i++) {
        float4 o;
        o.x = fmaxf(acc[i][0] + bb.x, 0.f);
        o.y = fmaxf(acc[i][1] + bb.y, 0.f);
        o.z = fmaxf(acc[i][2] + bb.z, 0.f);
        o.w = fmaxf(acc[i][3] + bb.w, 0.f);
        *(float4*)(O + (size_t)(m0 + ty * 8 + i) * ldo + j0 + tx * 4) = o;
    }
}

// ---------------- final tiny GEMM + softmax ----------------
__global__ void k_final(const float* __restrict__ W3, const float* __restrict__ b3,
                        float* __restrict__ out) {
    int row = blockIdx.x * 8 + (threadIdx.x >> 5);
    int lane = threadIdx.x & 31;
    if (row >= BATCH) return;
    float s0 = 0.f, s1 = 0.f;
    for (int k = lane; k < D3; k += 32) {
        float a = g_m2[(size_t)row * D3 + k];
        s0 = fmaf(a, W3[k * 2 + 0], s0);
        s1 = fmaf(a, W3[k * 2 + 1], s1);
    }
#pragma unroll
    for (int o = 16; o; o >>= 1) {
        s0 += __shfl_down_sync(0xffffffffu, s0, o);
        s1 += __shfl_down_sync(0xffffffffu, s1, o);
    }
    if (lane == 0) {
        float l0 = s0 + b3[0], l1 = s1 + b3[1];
        float m = fmaxf(l0, l1);
        float e0 = expf(l0 - m), e1 = expf(l1 - m);
        float inv = 1.f / (e0 + e1);
        out[row * 2 + 0] = e0 * inv;
        out[row * 2 + 1] = e1 * inv;
    }
}

// ---------------- host launcher ----------------
extern "C" void kernel_launch(void* const* d_in, const int* in_sizes, int n_in,
                              void* d_out, int out_size) {
    const float* x = (const float*)d_in[0];
    const int* ei = (const int*)d_in[1];
    const float* ew = (const float*)d_in[2];
    const float* Wxz = (const float*)d_in[3];  const float* bxz = (const float*)d_in[4];
    const float* Whz = (const float*)d_in[5];  const float* bhz = (const float*)d_in[6];
    const float* Wxr = (const float*)d_in[7];  const float* bxr = (const float*)d_in[8];
    const float* Whr = (const float*)d_in[9];  const float* bhr = (const float*)d_in[10];
    const float* Wxh = (const float*)d_in[11]; const float* bxh = (const float*)d_in[12];
    const float* Whh = (const float*)d_in[13]; const float* bhh = (const float*)d_in[14];
    const float* W1 = (const float*)d_in[15];  const float* b1 = (const float*)d_in[16];
    const float* W2 = (const float*)d_in[17];  const float* b2 = (const float*)d_in[18];
    const float* W3 = (const float*)d_in[19];  const float* b3 = (const float*)d_in[20];
    float* out = (float*)d_out;

    float *p_H, *p_Tx, *p_HR, *p_WxP, *p_WhP, *p_WhhP, *p_m1, *p_m2;
    cudaGetSymbolAddress((void**)&p_H, g_H);
    cudaGetSymbolAddress((void**)&p_Tx, g_Tx);
    cudaGetSymbolAddress((void**)&p_HR, g_HR);
    cudaGetSymbolAddress((void**)&p_WxP, g_WxP);
    cudaGetSymbolAddress((void**)&p_WhP, g_WhP);
    cudaGetSymbolAddress((void**)&p_WhhP, g_WhhP);
    cudaGetSymbolAddress((void**)&p_m1, g_m1);
    cudaGetSymbolAddress((void**)&p_m2, g_m2);

    const int EW_GRID = (BN_NODES * FDIM + 255) / 256;
    const int EDGE_GRID = (NE + 255) / 256;
    const int SPMM_GRID = BN_NODES / 8;
    const int MMA_GRID = BN_NODES / 128;  // 640

    // graph preprocessing
    k_zero<<<EW_GRID, 256>>>();
    k_deg<<<EDGE_GRID, 256>>>(ei, ew);
    k_nw<<<EDGE_GRID, 256>>>(ei, ew);
    k_scan1<<<80, 1024>>>();
    k_scan2<<<1, 32>>>();
    k_scan3<<<80, 1024>>>();
    k_scatter<<<EDGE_GRID, 256>>>(ei);
    k_packW<<<(192 * (192 + 128 + 64) + 255) / 256, 256>>>(Wxz, Wxr, Wxh, Whz, Whr, Whh);

    for (int t = 0; t < T_STEPS; t++) {
        const float* xt = x + (size_t)t * BN_NODES * FDIM;

        // X basis + X-cheb GEMM -> g_gx
        k_spmm<<<SPMM_GRID, 256>>>(xt, FDIM, p_Tx, 128, nullptr, 0, 1.f);
        k_spmm<<<SPMM_GRID, 256>>>(p_Tx, 128, p_Tx + 64, 128, xt, FDIM, 2.f);
        k_mma<192, 0><<<MMA_GRID, 256>>>(xt, FDIM, p_Tx, p_WxP,
                                         nullptr, nullptr, nullptr, nullptr);

        // H basis + gates GEMM (writes g_Z, g_HR)
        k_spmm<<<SPMM_GRID, 256>>>(p_H, FDIM, p_Tx, 128, nullptr, 0, 1.f);
        k_spmm<<<SPMM_GRID, 256>>>(p_Tx, 128, p_Tx + 64, 128, p_H, FDIM, 2.f);
        k_mma<128, 2><<<MMA_GRID, 256>>>(p_H, FDIM, p_Tx, p_WhP, bxz, bhz, bxr, bhr);

        // HR basis + update GEMM (writes g_H)
        k_spmm<<<SPMM_GRID, 256>>>(p_HR, FDIM, p_Tx, 128, nullptr, 0, 1.f);
        k_spmm<<<SPMM_GRID, 256>>>(p_Tx, 128, p_Tx + 64, 128, p_HR, FDIM, 2.f);
        k_mma<64, 3><<<MMA_GRID, 256>>>(p_HR, FDIM, p_Tx, p_WhhP,
                                        bxh, bhh, nullptr, nullptr);
    }

    // MLP head on H viewed as [4096, 1280]
    k_gemm_relu<<<dim3(BATCH / 128, D2 / 64), 256>>>(p_H, D1, W1, D2, b1, p_m1, D2, D1);
    k_gemm_relu<<<dim3(BATCH / 128, D3 / 64), 256>>>(p_m1, D2, W2, D3, b2, p_m2, D3, D2);
    k_final<<<BATCH / 8, 256>>>(W3, b3, out);
}